// round 12
// baseline (speedup 1.0000x reference)
#include <cuda_runtime.h>

// spixel_upsample2d: out[b, 4h+a, 4w+d] = sum_{c<2, ky<3, kx<3}
//     cv[b, c, h+ky-1, w+kx-1] * sp[b, c*9 + ky*3+kx, 4h+a, 4w+d]
// cv: (4,2,128,256) fp32 (1 MB, L2-resident)  sp: (4,18,512,1024) fp32 (151 MB streamed)
// out: (4,1,512,1024) fp32 (8.4 MB)
//
// R11: final config sweep point. R8 body (best ncu: 25.98us, DRAM 77.3%) with
// the 18 sp loads staged as two 9-deep batches (~76 regs) so occupancy rises
// 16 -> 24 warps/SM (launch_bounds occ 3). Tests the last untried point on the
// (warps x per-warp-MLP) curve; everything else measured 76-77% DRAM = device
// ceiling for this 95:5 read:write streaming mix.

#define BB 4
#define CC 2
#define HH 128
#define WW 256
#define H4 512
#define W4 1024

__global__ __launch_bounds__(256, 3)
void spixel_up_kernel(const float* __restrict__ cv,
                      const float* __restrict__ sp,
                      float* __restrict__ out) {
    const int w  = threadIdx.x;            // coarse column 0..255
    const int by = blockIdx.x;             // 0..2047 = b*512 + y
    const int y  = by & (H4 - 1);          // output row
    const int b  = by >> 9;                // batch
    const int h  = y >> 2;                 // coarse row

    const size_t ch_stride4 = (size_t)H4 * W4 / 4;   // float4 per sp channel
    const float4* __restrict__ spb =
        reinterpret_cast<const float4*>(sp) +
        (size_t)b * 18 * ch_stride4 + (size_t)y * (W4 / 4) + w;

    // ---- batch 0: 9 independent LDG.128 in flight ----
    float4 s0[9];
#pragma unroll
    for (int j = 0; j < 9; j++)
        s0[j] = spb[(size_t)j * ch_stride4];

    // ---- 18 patch values (L1/L2-hot; overlaps sp latency) ----
    float p[18];
#pragma unroll
    for (int c = 0; c < CC; c++) {
        const float* __restrict__ xb = cv + ((size_t)(b * CC + c) * HH) * WW;
#pragma unroll
        for (int ky = 0; ky < 3; ky++) {
            const int hh = h + ky - 1;
            const bool hv = (hh >= 0) && (hh < HH);
#pragma unroll
            for (int kx = 0; kx < 3; kx++) {
                const int wwc = w + kx - 1;
                const bool v = hv && (wwc >= 0) && (wwc < WW);
                p[c * 9 + ky * 3 + kx] = v ? __ldg(&xb[(size_t)hh * WW + wwc]) : 0.0f;
            }
        }
    }

    float4 acc = make_float4(0.f, 0.f, 0.f, 0.f);

    // ---- batch 1 issues while batch 0 is consumed ----
    float4 s1[9];
#pragma unroll
    for (int j = 0; j < 9; j++)
        s1[j] = spb[(size_t)(9 + j) * ch_stride4];

#pragma unroll
    for (int j = 0; j < 9; j++) {
        acc.x = fmaf(p[j], s0[j].x, acc.x);
        acc.y = fmaf(p[j], s0[j].y, acc.y);
        acc.z = fmaf(p[j], s0[j].z, acc.z);
        acc.w = fmaf(p[j], s0[j].w, acc.w);
    }
#pragma unroll
    for (int j = 0; j < 9; j++) {
        acc.x = fmaf(p[9 + j], s1[j].x, acc.x);
        acc.y = fmaf(p[9 + j], s1[j].y, acc.y);
        acc.z = fmaf(p[9 + j], s1[j].z, acc.z);
        acc.w = fmaf(p[9 + j], s1[j].w, acc.w);
    }

    reinterpret_cast<float4*>(out)[(size_t)b * H4 * (W4 / 4) +
                                   (size_t)y * (W4 / 4) + w] = acc;
}

extern "C" void kernel_launch(void* const* d_in, const int* in_sizes, int n_in,
                              void* d_out, int out_size) {
    // Bind inputs by element count (robust to metadata ordering).
    const int CV_N = BB * CC * HH * WW;          // 262144
    const float* cv = nullptr;
    const float* sp = nullptr;
    for (int i = 0; i < n_in; i++) {
        if (in_sizes[i] == CV_N) cv = (const float*)d_in[i];
        else                     sp = (const float*)d_in[i];
    }
    float* out = (float*)d_out;

    dim3 grid(BB * H4);      // 2048 CTAs: one per (b, output row)
    dim3 block(256);         // one thread per float4 of the row
    spixel_up_kernel<<<grid, block>>>(cv, sp, out);
}

// round 13
// speedup vs baseline: 1.0767x; 1.0767x over previous
#include <cuda_runtime.h>

// spixel_upsample2d: out[b, 4h+a, 4w+d] = sum_{c<2, ky<3, kx<3}
//     cv[b, c, h+ky-1, w+kx-1] * sp[b, c*9 + ky*3+kx, 4h+a, 4w+d]
// cv: (4,2,128,256) fp32 (1 MB, L2-resident)  sp: (4,18,512,1024) fp32 (151 MB streamed)
// out: (4,1,512,1024) fp32 (8.4 MB)
//
// R12: R8's staged-18-load body (best isolated-launch time: 25.98us, DRAM 77.3%)
// on R3's schedule (128-thr CTAs, grid 4096) with streaming cache hints.
// R3 was the only config whose graph-replay wall time tracked its ncu time
// (27.2 vs 26.7; all others pay +3.2-3.5us). Theory: __stcs/__ldcs evict-first
// lines keep L2 clean of dirty out/sp residue between back-to-back replays --
// invisible to ncu's cache-flushed single-launch capture, real in the timed loop.

#define BB 4
#define CC 2
#define HH 128
#define WW 256
#define H4 512
#define W4 1024

__global__ __launch_bounds__(128, 4)
void spixel_up_kernel(const float* __restrict__ cv,
                      const float* __restrict__ sp,
                      float* __restrict__ out) {
    const int bid  = blockIdx.x;                 // 0..4095
    const int half = bid & 1;                    // which half-row
    const int y    = (bid >> 1) & (H4 - 1);      // output row 0..511
    const int b    = bid >> 10;                  // batch
    const int w    = half * 128 + threadIdx.x;   // coarse column 0..255
    const int h    = y >> 2;                     // coarse row

    const size_t ch_stride4 = (size_t)H4 * W4 / 4;   // float4 per sp channel
    const float4* __restrict__ spb =
        reinterpret_cast<const float4*>(sp) +
        (size_t)b * 18 * ch_stride4 + (size_t)y * (W4 / 4) + w;

    // ---- issue all 18 independent streaming LDG.128 first (full MLP) ----
    float4 s[18];
#pragma unroll
    for (int j = 0; j < 18; j++)
        s[j] = __ldcs(&spb[(size_t)j * ch_stride4]);   // evict-first: no reuse

    // ---- 18 patch values (L1/L2-hot; overlaps sp latency) ----
    float p[18];
#pragma unroll
    for (int c = 0; c < CC; c++) {
        const float* __restrict__ xb = cv + ((size_t)(b * CC + c) * HH) * WW;
#pragma unroll
        for (int ky = 0; ky < 3; ky++) {
            const int hh = h + ky - 1;
            const bool hv = (hh >= 0) && (hh < HH);
#pragma unroll
            for (int kx = 0; kx < 3; kx++) {
                const int wwc = w + kx - 1;
                const bool v = hv && (wwc >= 0) && (wwc < WW);
                p[c * 9 + ky * 3 + kx] = v ? __ldg(&xb[(size_t)hh * WW + wwc]) : 0.0f;
            }
        }
    }

    // ---- FMA chain ----
    float4 acc = make_float4(0.f, 0.f, 0.f, 0.f);
#pragma unroll
    for (int j = 0; j < 18; j++) {
        acc.x = fmaf(p[j], s[j].x, acc.x);
        acc.y = fmaf(p[j], s[j].y, acc.y);
        acc.z = fmaf(p[j], s[j].z, acc.z);
        acc.w = fmaf(p[j], s[j].w, acc.w);
    }

    // Streaming store: out has no reuse within a launch; evict-first keeps the
    // dirty set small so the next graph replay starts against a clean L2.
    __stcs(&reinterpret_cast<float4*>(out)[(size_t)b * H4 * (W4 / 4) +
                                           (size_t)y * (W4 / 4) + w], acc);
}

extern "C" void kernel_launch(void* const* d_in, const int* in_sizes, int n_in,
                              void* d_out, int out_size) {
    // Bind inputs by element count (robust to metadata ordering).
    const int CV_N = BB * CC * HH * WW;          // 262144
    const float* cv = nullptr;
    const float* sp = nullptr;
    for (int i = 0; i < n_in; i++) {
        if (in_sizes[i] == CV_N) cv = (const float*)d_in[i];
        else                     sp = (const float*)d_in[i];
    }
    float* out = (float*)d_out;

    dim3 grid(BB * H4 * 2);   // 4096 CTAs: one per (b, row, half-row)
    dim3 block(128);          // one thread per float4 in the half-row
    spixel_up_kernel<<<grid, block>>>(cv, sp, out);
}